// round 15
// baseline (speedup 1.0000x reference)
#include <cuda_runtime.h>
#include <cuda_bf16.h>
#include <math.h>
#include <stdint.h>

#define BATCH   32
#define L_TOK   196
#define D_MODEL 512
#define D_INNER 1024
#define PATCH_D 768
#define N_STATE 16
#define N_LAYER 6
#define M_ROWS  (BATCH * L_TOK)   // 6272

// ---------------- scratch (static device globals; no allocation) ----------
static __device__ float g_t    [M_ROWS * D_MODEL];
static __device__ float g_xz   [M_ROWS * 2 * D_INNER];
static __device__ float g_dtbc [M_ROWS * 64];
static __device__ float g_xpp  [4 * M_ROWS * 64];     // split-K partials
static __device__ float g_dt   [M_ROWS * D_INNER];
static __device__ float g_mo   [2 * M_ROWS * D_MODEL];  // split-K x2 partials
static __device__ float g_pool [BATCH * D_MODEL];
static __device__ __align__(16) __nv_bfloat16 g_ah[M_ROWS * D_INNER];
static __device__ __align__(16) __nv_bfloat16 g_al[M_ROWS * D_INNER];
// all weights hi/lo, converted once per call:
#define W_EMB_OFF 0
#define W_IN_OFF  (512 * 768)
#define W_XP_OFF  (W_IN_OFF + 6 * 2048 * 512)
#define W_OUT_OFF (W_XP_OFF + 6 * 64 * 1024)
#define W_TOTAL   (W_OUT_OFF + 6 * 512 * 1024)
static __device__ __align__(16) __nv_bfloat16 g_wh[W_TOTAL];
static __device__ __align__(16) __nv_bfloat16 g_wl[W_TOTAL];

__device__ __forceinline__ void split_hl(float v, __nv_bfloat16& h, __nv_bfloat16& l) {
    h = __float2bfloat16_rn(v);
    l = __float2bfloat16_rn(v - __bfloat162float(h));
}

// ---------------- fp32 -> bf16 hi/lo split --------------------------------
__global__ void cvt_hl(const float4* __restrict__ s,
                       uint2* __restrict__ hi, uint2* __restrict__ lo) {
    int i = blockIdx.x * 256 + threadIdx.x;
    float4 v = s[i];
    __nv_bfloat16 hx, hy, hz, hw, lx, ly, lz, lw;
    split_hl(v.x, hx, lx); split_hl(v.y, hy, ly);
    split_hl(v.z, hz, lz); split_hl(v.w, hw, lw);
    uint2 H, L;
    H.x = (uint32_t)__bfloat16_as_ushort(hx) | ((uint32_t)__bfloat16_as_ushort(hy) << 16);
    H.y = (uint32_t)__bfloat16_as_ushort(hz) | ((uint32_t)__bfloat16_as_ushort(hw) << 16);
    L.x = (uint32_t)__bfloat16_as_ushort(lx) | ((uint32_t)__bfloat16_as_ushort(ly) << 16);
    L.y = (uint32_t)__bfloat16_as_ushort(lz) | ((uint32_t)__bfloat16_as_ushort(lw) << 16);
    hi[i] = H; lo[i] = L;
}

// ---------------- HMMA helpers --------------------------------------------
__device__ __forceinline__ uint32_t smem_u32(const void* p) {
    uint32_t a;
    asm("{ .reg .u64 t; cvta.to.shared.u64 t, %1; cvt.u32.u64 %0, t; }"
        : "=r"(a) : "l"(p));
    return a;
}
__device__ __forceinline__ void ldm_x4(uint32_t* r, uint32_t addr) {
    asm volatile("ldmatrix.sync.aligned.m8n8.x4.shared.b16 {%0,%1,%2,%3}, [%4];"
                 : "=r"(r[0]), "=r"(r[1]), "=r"(r[2]), "=r"(r[3]) : "r"(addr));
}
__device__ __forceinline__ void mma_bf16(float* d, const uint32_t* a,
                                         uint32_t b0, uint32_t b1) {
    asm volatile("mma.sync.aligned.m16n8k16.row.col.f32.bf16.bf16.f32 "
                 "{%0,%1,%2,%3}, {%4,%5,%6,%7}, {%8,%9}, {%0,%1,%2,%3};"
                 : "+f"(d[0]), "+f"(d[1]), "+f"(d[2]), "+f"(d[3])
                 : "r"(a[0]), "r"(a[1]), "r"(a[2]), "r"(a[3]), "r"(b0), "r"(b1));
}

// ===== bf16x3 HMMA GEMM: C[M,N] = A[M,K] @ W[N,K]^T in ~fp32 ==============
// 256 threads, tile 128x64, BK=64, 2-stage cp.async, 2 CTAs/SM.
// 8 warps, warp tile 16x64. Row stride 144B -> ldmatrix conflict-free.
// Optional split-K over gridDim.z (bias applied on z==0 only).
#define ROWB 144
#define OFF_AL 18432
#define OFF_BH 36864
#define OFF_BL 46080
#define STG_BYTES 55296
#define GEMM_SMEM (2 * STG_BYTES)   // 110592

__global__ void __launch_bounds__(256, 2) gemm_tc(
    const __nv_bfloat16* __restrict__ Ah, const __nv_bfloat16* __restrict__ Al,
    const __nv_bfloat16* __restrict__ Bh, const __nv_bfloat16* __restrict__ Bl,
    const float* __restrict__ bias,
    float* __restrict__ C, int ldc, int K, int czstride)
{
    extern __shared__ char smem[];
    const uint32_t sbase = smem_u32(smem);
    const int tid = threadIdx.x;
    const int wid = tid >> 5, lane = tid & 31;
    const int m0 = blockIdx.y * 128, n0 = blockIdx.x * 64;
    const int kseg = K / gridDim.z;
    const int kb = blockIdx.z * kseg;
    C += (size_t)blockIdx.z * czstride;

    float acc[8][4];
#pragma unroll
    for (int j = 0; j < 8; j++)
#pragma unroll
        for (int q = 0; q < 4; q++) acc[j][q] = 0.f;

    const int niter = kseg >> 6;
    const int lr  = tid >> 3;          // 0..31
    const int kc16 = (tid & 7) * 16;
    const int kcel = (tid & 7) * 8;

    auto load_stage = [&](int st, int it) {
        uint32_t sb = sbase + st * STG_BYTES;
        const int k0 = kb + (it << 6);
#pragma unroll
        for (int q = 0; q < 4; q++) {          // A rows: 4 batches of 32
            int r = lr + q * 32;
            size_t gA = (size_t)(m0 + r) * K + k0 + kcel;
            uint32_t so = (uint32_t)(r * ROWB + kc16);
            asm volatile("cp.async.cg.shared.global [%0], [%1], 16;"
                         :: "r"(sb + so), "l"(Ah + gA) : "memory");
            asm volatile("cp.async.cg.shared.global [%0], [%1], 16;"
                         :: "r"(sb + OFF_AL + so), "l"(Al + gA) : "memory");
        }
#pragma unroll
        for (int q = 0; q < 2; q++) {          // B rows: 2 batches of 32
            int r = lr + q * 32;
            size_t gB = (size_t)(n0 + r) * K + k0 + kcel;
            uint32_t so = (uint32_t)(r * ROWB + kc16);
            asm volatile("cp.async.cg.shared.global [%0], [%1], 16;"
                         :: "r"(sb + OFF_BH + so), "l"(Bh + gB) : "memory");
            asm volatile("cp.async.cg.shared.global [%0], [%1], 16;"
                         :: "r"(sb + OFF_BL + so), "l"(Bl + gB) : "memory");
        }
        asm volatile("cp.async.commit_group;" ::: "memory");
    };

    load_stage(0, 0);

    const uint32_t aoff = (uint32_t)((wid * 16 + (lane & 15)) * ROWB + (lane >> 4) * 16);
    const uint32_t boff = (uint32_t)(((lane & 7) + ((lane & 16) >> 1)) * ROWB
                                     + ((lane & 8) ? 16 : 0));

    for (int it = 0; it < niter; it++) {
        if (it + 1 < niter) {
            load_stage((it + 1) & 1, it + 1);
            asm volatile("cp.async.wait_group 1;" ::: "memory");
        } else {
            asm volatile("cp.async.wait_group 0;" ::: "memory");
        }
        __syncthreads();

        uint32_t sb = sbase + (it & 1) * STG_BYTES;
        uint32_t sA_hi = sb + aoff;
        uint32_t sA_lo = sb + OFF_AL + aoff;
        uint32_t sB_hi = sb + OFF_BH + boff;
        uint32_t sB_lo = sb + OFF_BL + boff;
#pragma unroll
        for (int ks = 0; ks < 4; ks++) {
            uint32_t kbq = ks * 32;            // 16 bf16 = 32B per k-step
            uint32_t a_h[4], a_l[4];
            ldm_x4(a_h, sA_hi + kbq);
            ldm_x4(a_l, sA_lo + kbq);
#pragma unroll
            for (int nt = 0; nt < 4; nt++) {
                uint32_t b_h[4], b_l[4];
                ldm_x4(b_h, sB_hi + nt * (16 * ROWB) + kbq);
                ldm_x4(b_l, sB_lo + nt * (16 * ROWB) + kbq);
                mma_bf16(acc[2 * nt + 0], a_h, b_h[0], b_h[1]);
                mma_bf16(acc[2 * nt + 1], a_h, b_h[2], b_h[3]);
                mma_bf16(acc[2 * nt + 0], a_h, b_l[0], b_l[1]);
                mma_bf16(acc[2 * nt + 1], a_h, b_l[2], b_l[3]);
                mma_bf16(acc[2 * nt + 0], a_l, b_h[0], b_h[1]);
                mma_bf16(acc[2 * nt + 1], a_l, b_h[2], b_h[3]);
            }
        }
        __syncthreads();
    }

    const bool addb = (bias != nullptr) && (blockIdx.z == 0);
    const int mrow = m0 + wid * 16 + (lane >> 2);
    const int ncol = n0 + (lane & 3) * 2;
#pragma unroll
    for (int j = 0; j < 8; j++) {
        int c = ncol + j * 8;
        float b0 = 0.f, b1 = 0.f;
        if (addb) { b0 = __ldg(&bias[c]); b1 = __ldg(&bias[c + 1]); }
        float2 v0 = make_float2(acc[j][0] + b0, acc[j][1] + b1);
        float2 v1 = make_float2(acc[j][2] + b0, acc[j][3] + b1);
        *(float2*)&C[(size_t)mrow * ldc + c] = v0;
        *(float2*)&C[(size_t)(mrow + 8) * ldc + c] = v1;
    }
}

// ------------- reduce split-K partials: dtbc = sum of 4 chunks ------------
__global__ void reduce_xp_kernel() {
    int i = blockIdx.x * 256 + threadIdx.x;
    const float4* p = (const float4*)g_xpp;
    const int S = M_ROWS * 64 / 4;
    float4 a = p[i], b = p[i + S], c = p[i + 2 * S], d = p[i + 3 * S];
    float4 r;
    r.x = (a.x + b.x) + (c.x + d.x);
    r.y = (a.y + b.y) + (c.y + d.y);
    r.z = (a.z + b.z) + (c.z + d.z);
    r.w = (a.w + b.w) + (c.w + d.w);
    ((float4*)g_dtbc)[i] = r;
}

// ---------------- patchify + LayerNorm(768) -> bf16 hi/lo -----------------
__global__ void patchify_ln_kernel(const float* __restrict__ x,
                                   const float* __restrict__ gam,
                                   const float* __restrict__ bet) {
    int row = blockIdx.x;
    int b = row / L_TOK, l = row % L_TOK;
    int gh = l / 14, gw = l % 14;
    int tid = threadIdx.x;
    float v[3];
    float s = 0.f, s2 = 0.f;
#pragma unroll
    for (int i = 0; i < 3; i++) {
        int e = tid + i * 256;
        int c = e >> 8, rem = e & 255;
        int p1 = rem >> 4, p2 = rem & 15;
        float val = x[(((size_t)b * 3 + c) * 224 + gh * 16 + p1) * 224 + gw * 16 + p2];
        v[i] = val; s += val; s2 += val * val;
    }
#pragma unroll
    for (int off = 16; off > 0; off >>= 1) {
        s  += __shfl_xor_sync(0xFFFFFFFFu, s, off);
        s2 += __shfl_xor_sync(0xFFFFFFFFu, s2, off);
    }
    __shared__ float ws[8][2];
    int wid = tid >> 5;
    if ((tid & 31) == 0) { ws[wid][0] = s; ws[wid][1] = s2; }
    __syncthreads();
    float S = 0.f, S2 = 0.f;
#pragma unroll
    for (int w = 0; w < 8; w++) { S += ws[w][0]; S2 += ws[w][1]; }
    float mu  = S * (1.f / 768.f);
    float var = S2 * (1.f / 768.f) - mu * mu;
    float inv = rsqrtf(var + 1e-5f);
#pragma unroll
    for (int i = 0; i < 3; i++) {
        int e = tid + i * 256;
        float o = (v[i] - mu) * inv * gam[e] + bet[e];
        __nv_bfloat16 h, lo2;
        split_hl(o, h, lo2);
        g_ah[(size_t)row * PATCH_D + e] = h;
        g_al[(size_t)row * PATCH_D + e] = lo2;
    }
}

// ---------------- small fp32 NT GEMM (dt_proj) ----------------------------
template<int BM, int BN, int BK, int TM, int TN, int EPI>
__global__ void __launch_bounds__(256) gemm_nt(
    const float* __restrict__ A, int lda,
    const float* __restrict__ W, int Kd,
    const float* __restrict__ bias,
    float* __restrict__ C, int ldc)
{
    __shared__ float As[BK][BM + 4];
    __shared__ float Bs[BK][BN + 4];
    const int m0 = blockIdx.y * BM, n0 = blockIdx.x * BN;
    const int tid = threadIdx.x;
    const int tx = tid & 15, ty = tid >> 4;
    constexpr int KQ = BK / 4;
    const int lrow = tid / KQ;
    const int kq   = (tid % KQ) * 4;

    float acc[TM][TN];
#pragma unroll
    for (int i = 0; i < TM; i++)
#pragma unroll
        for (int j = 0; j < TN; j++) acc[i][j] = 0.f;

    const float* Aptr = A + (size_t)(m0 + lrow) * lda + kq;
    const float* Wptr = W + (size_t)(n0 + lrow) * Kd  + kq;

    for (int k0 = 0; k0 < Kd; k0 += BK) {
        float4 a4 = *(const float4*)(Aptr + k0);
        float4 b4 = *(const float4*)(Wptr + k0);
        As[kq + 0][lrow] = a4.x; As[kq + 1][lrow] = a4.y;
        As[kq + 2][lrow] = a4.z; As[kq + 3][lrow] = a4.w;
        Bs[kq + 0][lrow] = b4.x; Bs[kq + 1][lrow] = b4.y;
        Bs[kq + 2][lrow] = b4.z; Bs[kq + 3][lrow] = b4.w;
        __syncthreads();
#pragma unroll
        for (int k = 0; k < BK; k++) {
            float ra[TM], rb[TN];
#pragma unroll
            for (int i = 0; i < TM; i++) ra[i] = As[k][ty + 16 * i];
#pragma unroll
            for (int j = 0; j < TN; j++) rb[j] = Bs[k][tx + 16 * j];
#pragma unroll
            for (int i = 0; i < TM; i++)
#pragma unroll
                for (int j = 0; j < TN; j++) acc[i][j] += ra[i] * rb[j];
        }
        __syncthreads();
    }
#pragma unroll
    for (int i = 0; i < TM; i++) {
        int r = m0 + ty + 16 * i;
#pragma unroll
        for (int j = 0; j < TN; j++) {
            int cc = n0 + tx + 16 * j;
            float v = acc[i][j];
            if (bias) v += __ldg(&bias[cc]);
            if (EPI == 1) v = (v > 20.f) ? v : log1pf(__expf(v));
            C[(size_t)r * ldc + cc] = v;
        }
    }
}

// -------- causal depthwise conv (K=4) + SiLU -> bf16 hi/lo only -----------
__global__ void conv_silu_kernel(const float* __restrict__ cw,
                                 const float* __restrict__ cb) {
    int idx = blockIdx.x * 256 + threadIdx.x;
    int d  = idx & (D_INNER - 1);
    int bl = idx >> 10;
    int l  = bl % L_TOK;
    float w0 = cw[d * 4 + 0], w1 = cw[d * 4 + 1];
    float w2 = cw[d * 4 + 2], w3 = cw[d * 4 + 3];
    size_t base = (size_t)bl * 2048 + d;
    float s = cb[d];
    if (l >= 3) s += w0 * g_xz[base - 3 * 2048];
    if (l >= 2) s += w1 * g_xz[base - 2 * 2048];
    if (l >= 1) s += w2 * g_xz[base - 1 * 2048];
    s += w3 * g_xz[base];
    s = s / (1.f + __expf(-s));
    __nv_bfloat16 h, lo2;
    split_hl(s, h, lo2);
    g_ah[idx] = h;
    g_al[idx] = lo2;
}

// --- selective scan, fused conv+silu; 2 threads per (b,d) -----------------
// Short-dependency version: log-depth G powers, pipelined exps, y tree.
__global__ void __launch_bounds__(64) scan_kernel(
    const float* __restrict__ A_log, const float* __restrict__ Dv,
    const float* __restrict__ cw, const float* __restrict__ cb)
{
    int t = blockIdx.x * 64 + threadIdx.x;       // 65536 threads
    int half = t & 1;
    int bd = t >> 1;
    int b = bd >> 10, d = bd & 1023;
    int n0 = half * 8;
    float a[8], h[8];
#pragma unroll
    for (int n = 0; n < 8; n++) {
        a[n] = -__expf(__ldg(&A_log[d * N_STATE + n0 + n]));
        h[n] = 0.f;
    }
    float a0 = a[0];
    float delta = (a[7] - a[0]) * (1.f / 7.f);
    bool ap = true;
#pragma unroll
    for (int n = 0; n < 8; n++)
        ap = ap && (fabsf(a[n] - (a0 + n * delta)) <= 1e-5f * fmaxf(fabsf(a[n]), 1e-3f));

    float w0 = __ldg(&cw[d * 4 + 0]), w1 = __ldg(&cw[d * 4 + 1]);
    float w2 = __ldg(&cw[d * 4 + 2]), w3 = __ldg(&cw[d * 4 + 3]);
    float cbd = __ldg(&cb[d]);
    float Dd = __ldg(&Dv[d]);
    size_t row0 = (size_t)b * L_TOK;

    float dtv = g_dt[row0 * 1024 + d];
    float xs  = g_xz[row0 * 2048 + d];
    float zv  = g_xz[row0 * 2048 + 1024 + d];
    float xm1 = 0.f, xm2 = 0.f, xm3 = 0.f;
    const float4* bc4 = (const float4*)(g_dtbc + row0 * 64 + 32 + n0);
    float4 Bv0 = bc4[0], Bv1 = bc4[1];
    float4 Cv0 = bc4[4], Cv1 = bc4[5];
    // pipelined exps for the CURRENT step
    float eA = __expf(dtv * a0);
    float eG = __expf(dtv * delta);
    for (int l = 0; l < L_TOK; l++) {
        float dtn = 0.f, xn = 0.f, zn = 0.f;
        float4 nB0, nB1, nC0, nC1;
        float neA = 0.f, neG = 0.f;
        if (l + 1 < L_TOK) {
            size_t rn = row0 + l + 1;
            dtn = g_dt[rn * 1024 + d];
            xn  = g_xz[rn * 2048 + d];
            zn  = g_xz[rn * 2048 + 1024 + d];
            const float4* nbc = (const float4*)(g_dtbc + rn * 64 + 32 + n0);
            nB0 = nbc[0]; nB1 = nbc[1]; nC0 = nbc[4]; nC1 = nbc[5];
            if (ap) { neA = __expf(dtn * a0); neG = __expf(dtn * delta); }
        }
        float xc = cbd + w0 * xm3 + w1 * xm2 + w2 * xm1 + w3 * xs;
        xc = xc / (1.f + __expf(-xc));

        float Bv[8] = {Bv0.x, Bv0.y, Bv0.z, Bv0.w, Bv1.x, Bv1.y, Bv1.z, Bv1.w};
        float Cv[8] = {Cv0.x, Cv0.y, Cv0.z, Cv0.w, Cv1.x, Cv1.y, Cv1.z, Cv1.w};
        float dx = dtv * xc;
        float y;
        if (ap) {
            // log-depth power tree: dA_n = eA * eG^n, all independent FMAs
            float G2 = eG * eG;
            float G3 = G2 * eG;
            float G4 = G2 * G2;
            float dA[8];
            dA[0] = eA;
            dA[1] = eA * eG;
            dA[2] = eA * G2;
            dA[3] = eA * G3;
            dA[4] = eA * G4;
            dA[5] = dA[1] * G4;
            dA[6] = dA[2] * G4;
            dA[7] = dA[3] * G4;
#pragma unroll
            for (int n = 0; n < 8; n++)
                h[n] = fmaf(dA[n], h[n], dx * Bv[n]);
        } else {
#pragma unroll
            for (int n = 0; n < 8; n++) {
                float dAn = __expf(dtv * a[n]);
                h[n] = fmaf(dAn, h[n], dx * Bv[n]);
            }
        }
        // y: 4-way tree reduction
        float y0 = fmaf(h[0], Cv[0], h[4] * Cv[4]);
        float y1 = fmaf(h[1], Cv[1], h[5] * Cv[5]);
        float y2 = fmaf(h[2], Cv[2], h[6] * Cv[6]);
        float y3 = fmaf(h[3], Cv[3], h[7] * Cv[7]);
        y = (y0 + y1) + (y2 + y3);
        y += __shfl_xor_sync(0xFFFFFFFFu, y, 1);
        float yy = fmaf(xc, Dd, y);
        yy *= zv / (1.f + __expf(-zv));
        size_t oi = (row0 + l) * 1024 + d;
        __nv_bfloat16 hi = __float2bfloat16_rn(yy);
        if (half == 0) {
            g_ah[oi] = hi;
        } else {
            g_al[oi] = __float2bfloat16_rn(yy - __bfloat162float(hi));
        }
        xm3 = xm2; xm2 = xm1; xm1 = xs; xs = xn;
        dtv = dtn; zv = zn;
        eA = neA; eG = neG;
        Bv0 = nB0; Bv1 = nB1; Cv0 = nC0; Cv1 = nC1;
    }
}

// -- LayerNorm(512) over (inp [+ inp2] [+ res]); emits fp32 + bf16 hi/lo ---
__global__ void ln512_kernel(const float* __restrict__ inp,
                             const float* __restrict__ inp2,
                             const float* __restrict__ res,
                             const float* __restrict__ gam,
                             const float* __restrict__ bet,
                             float* __restrict__ out) {
    int row = blockIdx.x, tid = threadIdx.x;
    size_t base = (size_t)row * 512;
    float v0 = inp[base + tid], v1 = inp[base + tid + 256];
    if (inp2) { v0 += inp2[base + tid]; v1 += inp2[base + tid + 256]; }
    if (res)  { v0 += res[base + tid];  v1 += res[base + tid + 256]; }
    float s = v0 + v1, s2 = v0 * v0 + v1 * v1;
#pragma unroll
    for (int off = 16; off > 0; off >>= 1) {
        s  += __shfl_xor_sync(0xFFFFFFFFu, s, off);
        s2 += __shfl_xor_sync(0xFFFFFFFFu, s2, off);
    }
    __shared__ float ws[8][2];
    int wid = tid >> 5;
    if ((tid & 31) == 0) { ws[wid][0] = s; ws[wid][1] = s2; }
    __syncthreads();
    float S = 0.f, S2 = 0.f;
#pragma unroll
    for (int w = 0; w < 8; w++) { S += ws[w][0]; S2 += ws[w][1]; }
    float mu  = S * (1.f / 512.f);
    float var = S2 * (1.f / 512.f) - mu * mu;
    float inv = rsqrtf(var + 1e-5f);
    float o0 = (v0 - mu) * inv * gam[tid]       + bet[tid];
    float o1 = (v1 - mu) * inv * gam[tid + 256] + bet[tid + 256];
    out[base + tid]       = o0;
    out[base + tid + 256] = o1;
    __nv_bfloat16 h0, l0, h1, l1;
    split_hl(o0, h0, l0); split_hl(o1, h1, l1);
    g_ah[base + tid] = h0;       g_al[base + tid] = l0;
    g_ah[base + tid + 256] = h1; g_al[base + tid + 256] = l1;
}

// ---------------- mean pool over L ----------------------------------------
__global__ void pool_kernel() {
    int idx = blockIdx.x * 256 + threadIdx.x;
    int b = idx >> 9, d = idx & 511;
    float s = 0.f;
    for (int l = 0; l < L_TOK; l++)
        s += g_t[((size_t)b * L_TOK + l) * 512 + d];
    g_pool[idx] = s * (1.f / (float)L_TOK);
}

// ---------------- head ----------------------------------------------------
__global__ void head_kernel(const float* __restrict__ Wh,
                            const float* __restrict__ bh,
                            float* __restrict__ out) {
    int idx = threadIdx.x;
    if (idx >= BATCH * 10) return;
    int b = idx / 10, c = idx % 10;
    float s = bh[c];
    for (int k = 0; k < 512; k++)
        s += g_pool[b * 512 + k] * Wh[c * 512 + k];
    out[idx] = s;
}

// ---------------- launch ---------------------------------------------------
extern "C" void kernel_launch(void* const* d_in, const int* in_sizes, int n_in,
                              void* d_out, int out_size) {
    const float* x      = (const float*)d_in[0];
    const float* ln0_g  = (const float*)d_in[1];
    const float* ln0_b  = (const float*)d_in[2];
    const float* W_emb  = (const float*)d_in[3];
    const float* b_emb  = (const float*)d_in[4];
    const float* ln1_g  = (const float*)d_in[5];
    const float* ln1_b  = (const float*)d_in[6];
    const float* in_w   = (const float*)d_in[7];
    const float* conv_w = (const float*)d_in[8];
    const float* conv_b = (const float*)d_in[9];
    const float* xp_w   = (const float*)d_in[10];
    const float* dt_w   = (const float*)d_in[11];
    const float* dt_b   = (const float*)d_in[12];
    const float* A_log  = (const float*)d_in[13];
    const float* D_p    = (const float*)d_in[14];
    const float* out_w  = (const float*)d_in[15];
    const float* bln_g  = (const float*)d_in[16];
    const float* bln_b  = (const float*)d_in[17];
    const float* W_head = (const float*)d_in[18];
    const float* b_head = (const float*)d_in[19];
    float* out = (float*)d_out;

    float *t, *xz, *dtbc, *xpp, *dt, *mo;
    __nv_bfloat16 *ah, *al, *wh, *wl;
    cudaGetSymbolAddress((void**)&t,     g_t);
    cudaGetSymbolAddress((void**)&xz,    g_xz);
    cudaGetSymbolAddress((void**)&dtbc,  g_dtbc);
    cudaGetSymbolAddress((void**)&xpp,   g_xpp);
    cudaGetSymbolAddress((void**)&dt,    g_dt);
    cudaGetSymbolAddress((void**)&mo,    g_mo);
    cudaGetSymbolAddress((void**)&ah,    g_ah);
    cudaGetSymbolAddress((void**)&al,    g_al);
    cudaGetSymbolAddress((void**)&wh,    g_wh);
    cudaGetSymbolAddress((void**)&wl,    g_wl);

    cudaFuncSetAttribute(gemm_tc, cudaFuncAttributeMaxDynamicSharedMemorySize,
                         GEMM_SMEM);

    // ---- convert all weights to bf16 hi/lo upfront ----
    cvt_hl<<<(512 * PATCH_D) / 1024, 256>>>(
        (const float4*)W_emb, (uint2*)(wh + W_EMB_OFF), (uint2*)(wl + W_EMB_OFF));
    cvt_hl<<<(6 * 2048 * 512) / 1024, 256>>>(
        (const float4*)in_w, (uint2*)(wh + W_IN_OFF), (uint2*)(wl + W_IN_OFF));
    cvt_hl<<<(6 * 64 * 1024) / 1024, 256>>>(
        (const float4*)xp_w, (uint2*)(wh + W_XP_OFF), (uint2*)(wl + W_XP_OFF));
    cvt_hl<<<(6 * 512 * 1024) / 1024, 256>>>(
        (const float4*)out_w, (uint2*)(wh + W_OUT_OFF), (uint2*)(wl + W_OUT_OFF));

    // ---- patch embed (split-K x2, reduced inside ln512) ----
    patchify_ln_kernel<<<M_ROWS, 256>>>(x, ln0_g, ln0_b);
    gemm_tc<<<dim3(512 / 64, M_ROWS / 128, 2), 256, GEMM_SMEM>>>(
        ah, al, wh + W_EMB_OFF, wl + W_EMB_OFF, b_emb, mo, D_MODEL, PATCH_D,
        M_ROWS * D_MODEL);
    ln512_kernel<<<M_ROWS, 256>>>(mo, mo + (size_t)M_ROWS * D_MODEL, nullptr,
                                  ln1_g, ln1_b, t);

    for (int i = 0; i < N_LAYER; i++) {
        const __nv_bfloat16* inWh = wh + W_IN_OFF  + (size_t)i * 2048 * 512;
        const __nv_bfloat16* inWl = wl + W_IN_OFF  + (size_t)i * 2048 * 512;
        const __nv_bfloat16* xpWh = wh + W_XP_OFF  + (size_t)i * 64 * 1024;
        const __nv_bfloat16* xpWl = wl + W_XP_OFF  + (size_t)i * 64 * 1024;
        const __nv_bfloat16* oWh  = wh + W_OUT_OFF + (size_t)i * 512 * 1024;
        const __nv_bfloat16* oWl  = wl + W_OUT_OFF + (size_t)i * 512 * 1024;
        const float* cW   = conv_w + (size_t)i * 1024 * 4;
        const float* cB   = conv_b + (size_t)i * 1024;
        const float* dtW  = dt_w + (size_t)i * 1024 * 32;
        const float* dtB  = dt_b + (size_t)i * 1024;
        const float* Ai   = A_log + (size_t)i * 1024 * 16;
        const float* Di   = D_p + (size_t)i * 1024;
        const float* bg   = bln_g + (size_t)i * 512;
        const float* bb   = bln_b + (size_t)i * 512;

        // xz = t @ in_proj^T : (6272,512) x (2048,512)
        gemm_tc<<<dim3(2048 / 64, M_ROWS / 128, 1), 256, GEMM_SMEM>>>(
            ah, al, inWh, inWl, nullptr, xz, 2048, 512, 0);
        // conv + silu -> ah/al (bf16 hi/lo) for x_proj
        conv_silu_kernel<<<(M_ROWS * D_INNER) / 256, 256>>>(cW, cB);
        // x_dbl = xc @ x_proj^T : split-K x4, then reduce
        gemm_tc<<<dim3(1, M_ROWS / 128, 4), 256, GEMM_SMEM>>>(
            ah, al, xpWh, xpWl, nullptr, xpp, 64, 1024, M_ROWS * 64);
        reduce_xp_kernel<<<(M_ROWS * 64 / 4) / 256, 256>>>();
        // dt = softplus(x_dbl[:, :32] @ dt_proj^T + dt_b)
        gemm_nt<64,64,16,4,4,1><<<dim3(1024 / 64, M_ROWS / 64), 256>>>(
            dtbc, 64, dtW, 32, dtB, dt, D_INNER);
        // scan (conv fused) -> y hi/lo in ah/al
        scan_kernel<<<1024, 64>>>(Ai, Di, cW, cB);
        // out = y @ out_proj^T : split-K x2, reduced inside ln512
        gemm_tc<<<dim3(512 / 64, M_ROWS / 128, 2), 256, GEMM_SMEM>>>(
            ah, al, oWh, oWl, nullptr, mo, D_MODEL, 1024, M_ROWS * D_MODEL);
        ln512_kernel<<<M_ROWS, 256>>>(mo, mo + (size_t)M_ROWS * D_MODEL, t,
                                      bg, bb, t);
    }

    pool_kernel<<<(BATCH * D_MODEL) / 256, 256>>>();
    head_kernel<<<1, 320>>>(W_head, b_head, out);
}

// round 16
// speedup vs baseline: 1.0193x; 1.0193x over previous
#include <cuda_runtime.h>
#include <cuda_bf16.h>
#include <math.h>
#include <stdint.h>

#define BATCH   32
#define L_TOK   196
#define D_MODEL 512
#define D_INNER 1024
#define PATCH_D 768
#define N_STATE 16
#define N_LAYER 6
#define M_ROWS  (BATCH * L_TOK)   // 6272

// ---------------- scratch (static device globals; no allocation) ----------
static __device__ float g_t    [M_ROWS * D_MODEL];
static __device__ float g_xz   [M_ROWS * 2 * D_INNER];
static __device__ float g_dtbc [M_ROWS * 64];
static __device__ float g_xpp  [4 * M_ROWS * 64];     // split-K partials
static __device__ float g_dt   [M_ROWS * D_INNER];
static __device__ float g_mo   [2 * M_ROWS * D_MODEL];  // split-K x2 partials
static __device__ float g_pool [BATCH * D_MODEL];
static __device__ __align__(16) __nv_bfloat16 g_ah[M_ROWS * D_INNER];
static __device__ __align__(16) __nv_bfloat16 g_al[M_ROWS * D_INNER];
// reduced x_dbl as bf16 hi/lo (for tensor-path dt_proj)
static __device__ __align__(16) __nv_bfloat16 g_dh[M_ROWS * 64];
static __device__ __align__(16) __nv_bfloat16 g_dl[M_ROWS * 64];
// dt_proj weights zero-padded K 32->64, hi/lo (6 layers x 1024 x 64)
static __device__ __align__(16) __nv_bfloat16 g_dwh[N_LAYER * 1024 * 64];
static __device__ __align__(16) __nv_bfloat16 g_dwl[N_LAYER * 1024 * 64];
// all other weights hi/lo, converted once per call:
#define W_EMB_OFF 0
#define W_IN_OFF  (512 * 768)
#define W_XP_OFF  (W_IN_OFF + 6 * 2048 * 512)
#define W_OUT_OFF (W_XP_OFF + 6 * 64 * 1024)
#define W_TOTAL   (W_OUT_OFF + 6 * 512 * 1024)
static __device__ __align__(16) __nv_bfloat16 g_wh[W_TOTAL];
static __device__ __align__(16) __nv_bfloat16 g_wl[W_TOTAL];

__device__ __forceinline__ void split_hl(float v, __nv_bfloat16& h, __nv_bfloat16& l) {
    h = __float2bfloat16_rn(v);
    l = __float2bfloat16_rn(v - __bfloat162float(h));
}

// ---------------- fp32 -> bf16 hi/lo split --------------------------------
__global__ void cvt_hl(const float4* __restrict__ s,
                       uint2* __restrict__ hi, uint2* __restrict__ lo) {
    int i = blockIdx.x * 256 + threadIdx.x;
    float4 v = s[i];
    __nv_bfloat16 hx, hy, hz, hw, lx, ly, lz, lw;
    split_hl(v.x, hx, lx); split_hl(v.y, hy, ly);
    split_hl(v.z, hz, lz); split_hl(v.w, hw, lw);
    uint2 H, L;
    H.x = (uint32_t)__bfloat16_as_ushort(hx) | ((uint32_t)__bfloat16_as_ushort(hy) << 16);
    H.y = (uint32_t)__bfloat16_as_ushort(hz) | ((uint32_t)__bfloat16_as_ushort(hw) << 16);
    L.x = (uint32_t)__bfloat16_as_ushort(lx) | ((uint32_t)__bfloat16_as_ushort(ly) << 16);
    L.y = (uint32_t)__bfloat16_as_ushort(lz) | ((uint32_t)__bfloat16_as_ushort(lw) << 16);
    hi[i] = H; lo[i] = L;
}

// ------------- dt_proj weights: pad K 32->64 with zeros, hi/lo ------------
__global__ void cvt_pad_dtw(const float* __restrict__ dtw) {
    int i = blockIdx.x * 256 + threadIdx.x;   // over 6*1024*64
    int k = i & 63;
    int n = (i >> 6) & 1023;
    int layer = i >> 16;
    float v = (k < 32) ? dtw[((size_t)layer * 1024 + n) * 32 + k] : 0.f;
    __nv_bfloat16 h, l;
    split_hl(v, h, l);
    g_dwh[i] = h;
    g_dwl[i] = l;
}

// ---------------- HMMA helpers --------------------------------------------
__device__ __forceinline__ uint32_t smem_u32(const void* p) {
    uint32_t a;
    asm("{ .reg .u64 t; cvta.to.shared.u64 t, %1; cvt.u32.u64 %0, t; }"
        : "=r"(a) : "l"(p));
    return a;
}
__device__ __forceinline__ void ldm_x4(uint32_t* r, uint32_t addr) {
    asm volatile("ldmatrix.sync.aligned.m8n8.x4.shared.b16 {%0,%1,%2,%3}, [%4];"
                 : "=r"(r[0]), "=r"(r[1]), "=r"(r[2]), "=r"(r[3]) : "r"(addr));
}
__device__ __forceinline__ void mma_bf16(float* d, const uint32_t* a,
                                         uint32_t b0, uint32_t b1) {
    asm volatile("mma.sync.aligned.m16n8k16.row.col.f32.bf16.bf16.f32 "
                 "{%0,%1,%2,%3}, {%4,%5,%6,%7}, {%8,%9}, {%0,%1,%2,%3};"
                 : "+f"(d[0]), "+f"(d[1]), "+f"(d[2]), "+f"(d[3])
                 : "r"(a[0]), "r"(a[1]), "r"(a[2]), "r"(a[3]), "r"(b0), "r"(b1));
}

// ===== bf16x3 HMMA GEMM: C[M,N] = A[M,K] @ W[N,K]^T in ~fp32 ==============
// 256 threads, tile 128x64, BK=64, 2-stage cp.async, 2 CTAs/SM.
// 8 warps, warp tile 16x64. Row stride 144B -> ldmatrix conflict-free.
// Optional split-K over gridDim.z (bias applied on z==0 only).
// epi=1 -> softplus after bias.
#define ROWB 144
#define OFF_AL 18432
#define OFF_BH 36864
#define OFF_BL 46080
#define STG_BYTES 55296
#define GEMM_SMEM (2 * STG_BYTES)   // 110592

__global__ void __launch_bounds__(256, 2) gemm_tc(
    const __nv_bfloat16* __restrict__ Ah, const __nv_bfloat16* __restrict__ Al,
    const __nv_bfloat16* __restrict__ Bh, const __nv_bfloat16* __restrict__ Bl,
    const float* __restrict__ bias,
    float* __restrict__ C, int ldc, int K, int czstride, int epi)
{
    extern __shared__ char smem[];
    const uint32_t sbase = smem_u32(smem);
    const int tid = threadIdx.x;
    const int wid = tid >> 5, lane = tid & 31;
    const int m0 = blockIdx.y * 128, n0 = blockIdx.x * 64;
    const int kseg = K / gridDim.z;
    const int kb = blockIdx.z * kseg;
    C += (size_t)blockIdx.z * czstride;

    float acc[8][4];
#pragma unroll
    for (int j = 0; j < 8; j++)
#pragma unroll
        for (int q = 0; q < 4; q++) acc[j][q] = 0.f;

    const int niter = kseg >> 6;
    const int lr  = tid >> 3;          // 0..31
    const int kc16 = (tid & 7) * 16;
    const int kcel = (tid & 7) * 8;

    auto load_stage = [&](int st, int it) {
        uint32_t sb = sbase + st * STG_BYTES;
        const int k0 = kb + (it << 6);
#pragma unroll
        for (int q = 0; q < 4; q++) {          // A rows: 4 batches of 32
            int r = lr + q * 32;
            size_t gA = (size_t)(m0 + r) * K + k0 + kcel;
            uint32_t so = (uint32_t)(r * ROWB + kc16);
            asm volatile("cp.async.cg.shared.global [%0], [%1], 16;"
                         :: "r"(sb + so), "l"(Ah + gA) : "memory");
            asm volatile("cp.async.cg.shared.global [%0], [%1], 16;"
                         :: "r"(sb + OFF_AL + so), "l"(Al + gA) : "memory");
        }
#pragma unroll
        for (int q = 0; q < 2; q++) {          // B rows: 2 batches of 32
            int r = lr + q * 32;
            size_t gB = (size_t)(n0 + r) * K + k0 + kcel;
            uint32_t so = (uint32_t)(r * ROWB + kc16);
            asm volatile("cp.async.cg.shared.global [%0], [%1], 16;"
                         :: "r"(sb + OFF_BH + so), "l"(Bh + gB) : "memory");
            asm volatile("cp.async.cg.shared.global [%0], [%1], 16;"
                         :: "r"(sb + OFF_BL + so), "l"(Bl + gB) : "memory");
        }
        asm volatile("cp.async.commit_group;" ::: "memory");
    };

    load_stage(0, 0);

    const uint32_t aoff = (uint32_t)((wid * 16 + (lane & 15)) * ROWB + (lane >> 4) * 16);
    const uint32_t boff = (uint32_t)(((lane & 7) + ((lane & 16) >> 1)) * ROWB
                                     + ((lane & 8) ? 16 : 0));

    for (int it = 0; it < niter; it++) {
        if (it + 1 < niter) {
            load_stage((it + 1) & 1, it + 1);
            asm volatile("cp.async.wait_group 1;" ::: "memory");
        } else {
            asm volatile("cp.async.wait_group 0;" ::: "memory");
        }
        __syncthreads();

        uint32_t sb = sbase + (it & 1) * STG_BYTES;
        uint32_t sA_hi = sb + aoff;
        uint32_t sA_lo = sb + OFF_AL + aoff;
        uint32_t sB_hi = sb + OFF_BH + boff;
        uint32_t sB_lo = sb + OFF_BL + boff;
#pragma unroll
        for (int ks = 0; ks < 4; ks++) {
            uint32_t kbq = ks * 32;            // 16 bf16 = 32B per k-step
            uint32_t a_h[4], a_l[4];
            ldm_x4(a_h, sA_hi + kbq);
            ldm_x4(a_l, sA_lo + kbq);
#pragma unroll
            for (int nt = 0; nt < 4; nt++) {
                uint32_t b_h[4], b_l[4];
                ldm_x4(b_h, sB_hi + nt * (16 * ROWB) + kbq);
                ldm_x4(b_l, sB_lo + nt * (16 * ROWB) + kbq);
                mma_bf16(acc[2 * nt + 0], a_h, b_h[0], b_h[1]);
                mma_bf16(acc[2 * nt + 1], a_h, b_h[2], b_h[3]);
                mma_bf16(acc[2 * nt + 0], a_h, b_l[0], b_l[1]);
                mma_bf16(acc[2 * nt + 1], a_h, b_l[2], b_l[3]);
                mma_bf16(acc[2 * nt + 0], a_l, b_h[0], b_h[1]);
                mma_bf16(acc[2 * nt + 1], a_l, b_h[2], b_h[3]);
            }
        }
        __syncthreads();
    }

    const bool addb = (bias != nullptr) && (blockIdx.z == 0);
    const int mrow = m0 + wid * 16 + (lane >> 2);
    const int ncol = n0 + (lane & 3) * 2;
#pragma unroll
    for (int j = 0; j < 8; j++) {
        int c = ncol + j * 8;
        float b0 = 0.f, b1 = 0.f;
        if (addb) { b0 = __ldg(&bias[c]); b1 = __ldg(&bias[c + 1]); }
        float p00 = acc[j][0] + b0, p01 = acc[j][1] + b1;
        float p10 = acc[j][2] + b0, p11 = acc[j][3] + b1;
        if (epi) {
            p00 = (p00 > 20.f) ? p00 : log1pf(__expf(p00));
            p01 = (p01 > 20.f) ? p01 : log1pf(__expf(p01));
            p10 = (p10 > 20.f) ? p10 : log1pf(__expf(p10));
            p11 = (p11 > 20.f) ? p11 : log1pf(__expf(p11));
        }
        *(float2*)&C[(size_t)mrow * ldc + c] = make_float2(p00, p01);
        *(float2*)&C[(size_t)(mrow + 8) * ldc + c] = make_float2(p10, p11);
    }
}

// --- reduce split-K partials: dtbc = sum of 4 chunks; also bf16 hi/lo -----
__global__ void reduce_xp_kernel() {
    int i = blockIdx.x * 256 + threadIdx.x;
    const float4* p = (const float4*)g_xpp;
    const int S = M_ROWS * 64 / 4;
    float4 a = p[i], b = p[i + S], c = p[i + 2 * S], d = p[i + 3 * S];
    float4 r;
    r.x = (a.x + b.x) + (c.x + d.x);
    r.y = (a.y + b.y) + (c.y + d.y);
    r.z = (a.z + b.z) + (c.z + d.z);
    r.w = (a.w + b.w) + (c.w + d.w);
    ((float4*)g_dtbc)[i] = r;
    __nv_bfloat16 hx, hy, hz, hw, lx, ly, lz, lw;
    split_hl(r.x, hx, lx); split_hl(r.y, hy, ly);
    split_hl(r.z, hz, lz); split_hl(r.w, hw, lw);
    uint2 H, L;
    H.x = (uint32_t)__bfloat16_as_ushort(hx) | ((uint32_t)__bfloat16_as_ushort(hy) << 16);
    H.y = (uint32_t)__bfloat16_as_ushort(hz) | ((uint32_t)__bfloat16_as_ushort(hw) << 16);
    L.x = (uint32_t)__bfloat16_as_ushort(lx) | ((uint32_t)__bfloat16_as_ushort(ly) << 16);
    L.y = (uint32_t)__bfloat16_as_ushort(lz) | ((uint32_t)__bfloat16_as_ushort(lw) << 16);
    ((uint2*)g_dh)[i] = H;
    ((uint2*)g_dl)[i] = L;
}

// ---------------- patchify + LayerNorm(768) -> bf16 hi/lo -----------------
__global__ void patchify_ln_kernel(const float* __restrict__ x,
                                   const float* __restrict__ gam,
                                   const float* __restrict__ bet) {
    int row = blockIdx.x;
    int b = row / L_TOK, l = row % L_TOK;
    int gh = l / 14, gw = l % 14;
    int tid = threadIdx.x;
    float v[3];
    float s = 0.f, s2 = 0.f;
#pragma unroll
    for (int i = 0; i < 3; i++) {
        int e = tid + i * 256;
        int c = e >> 8, rem = e & 255;
        int p1 = rem >> 4, p2 = rem & 15;
        float val = x[(((size_t)b * 3 + c) * 224 + gh * 16 + p1) * 224 + gw * 16 + p2];
        v[i] = val; s += val; s2 += val * val;
    }
#pragma unroll
    for (int off = 16; off > 0; off >>= 1) {
        s  += __shfl_xor_sync(0xFFFFFFFFu, s, off);
        s2 += __shfl_xor_sync(0xFFFFFFFFu, s2, off);
    }
    __shared__ float ws[8][2];
    int wid = tid >> 5;
    if ((tid & 31) == 0) { ws[wid][0] = s; ws[wid][1] = s2; }
    __syncthreads();
    float S = 0.f, S2 = 0.f;
#pragma unroll
    for (int w = 0; w < 8; w++) { S += ws[w][0]; S2 += ws[w][1]; }
    float mu  = S * (1.f / 768.f);
    float var = S2 * (1.f / 768.f) - mu * mu;
    float inv = rsqrtf(var + 1e-5f);
#pragma unroll
    for (int i = 0; i < 3; i++) {
        int e = tid + i * 256;
        float o = (v[i] - mu) * inv * gam[e] + bet[e];
        __nv_bfloat16 h, lo2;
        split_hl(o, h, lo2);
        g_ah[(size_t)row * PATCH_D + e] = h;
        g_al[(size_t)row * PATCH_D + e] = lo2;
    }
}

// -------- causal depthwise conv (K=4) + SiLU -> bf16 hi/lo only -----------
__global__ void conv_silu_kernel(const float* __restrict__ cw,
                                 const float* __restrict__ cb) {
    int idx = blockIdx.x * 256 + threadIdx.x;
    int d  = idx & (D_INNER - 1);
    int bl = idx >> 10;
    int l  = bl % L_TOK;
    float w0 = cw[d * 4 + 0], w1 = cw[d * 4 + 1];
    float w2 = cw[d * 4 + 2], w3 = cw[d * 4 + 3];
    size_t base = (size_t)bl * 2048 + d;
    float s = cb[d];
    if (l >= 3) s += w0 * g_xz[base - 3 * 2048];
    if (l >= 2) s += w1 * g_xz[base - 2 * 2048];
    if (l >= 1) s += w2 * g_xz[base - 1 * 2048];
    s += w3 * g_xz[base];
    s = s / (1.f + __expf(-s));
    __nv_bfloat16 h, lo2;
    split_hl(s, h, lo2);
    g_ah[idx] = h;
    g_al[idx] = lo2;
}

// --- selective scan, fused causal conv+silu; 2 threads per (b,d) ----------
__global__ void __launch_bounds__(64) scan_kernel(
    const float* __restrict__ A_log, const float* __restrict__ Dv,
    const float* __restrict__ cw, const float* __restrict__ cb)
{
    int t = blockIdx.x * 64 + threadIdx.x;       // 65536 threads
    int half = t & 1;
    int bd = t >> 1;
    int b = bd >> 10, d = bd & 1023;
    int n0 = half * 8;
    float a[8], h[8];
#pragma unroll
    for (int n = 0; n < 8; n++) {
        a[n] = -__expf(__ldg(&A_log[d * N_STATE + n0 + n]));
        h[n] = 0.f;
    }
    float a0 = a[0];
    float delta = (a[7] - a[0]) * (1.f / 7.f);
    bool ap = true;
#pragma unroll
    for (int n = 0; n < 8; n++)
        ap = ap && (fabsf(a[n] - (a0 + n * delta)) <= 1e-5f * fmaxf(fabsf(a[n]), 1e-3f));

    float w0 = __ldg(&cw[d * 4 + 0]), w1 = __ldg(&cw[d * 4 + 1]);
    float w2 = __ldg(&cw[d * 4 + 2]), w3 = __ldg(&cw[d * 4 + 3]);
    float cbd = __ldg(&cb[d]);
    float Dd = __ldg(&Dv[d]);
    size_t row0 = (size_t)b * L_TOK;

    float dtv = g_dt[row0 * 1024 + d];
    float xs  = g_xz[row0 * 2048 + d];
    float zv  = g_xz[row0 * 2048 + 1024 + d];
    float xm1 = 0.f, xm2 = 0.f, xm3 = 0.f;
    const float4* bc4 = (const float4*)(g_dtbc + row0 * 64 + 32 + n0);
    float4 Bv0 = bc4[0], Bv1 = bc4[1];
    float4 Cv0 = bc4[4], Cv1 = bc4[5];
    for (int l = 0; l < L_TOK; l++) {
        float dtn = 0.f, xn = 0.f, zn = 0.f;
        float4 nB0, nB1, nC0, nC1;
        if (l + 1 < L_TOK) {
            size_t rn = row0 + l + 1;
            dtn = g_dt[rn * 1024 + d];
            xn  = g_xz[rn * 2048 + d];
            zn  = g_xz[rn * 2048 + 1024 + d];
            const float4* nbc = (const float4*)(g_dtbc + rn * 64 + 32 + n0);
            nB0 = nbc[0]; nB1 = nbc[1]; nC0 = nbc[4]; nC1 = nbc[5];
        }
        float xc = cbd + w0 * xm3 + w1 * xm2 + w2 * xm1 + w3 * xs;
        xc = xc / (1.f + __expf(-xc));

        float Bv[8] = {Bv0.x, Bv0.y, Bv0.z, Bv0.w, Bv1.x, Bv1.y, Bv1.z, Bv1.w};
        float Cv[8] = {Cv0.x, Cv0.y, Cv0.z, Cv0.w, Cv1.x, Cv1.y, Cv1.z, Cv1.w};
        float dx = dtv * xc;
        float y = 0.f;
        if (ap) {
            float dA = __expf(dtv * a0);
            float G  = __expf(dtv * delta);
#pragma unroll
            for (int n = 0; n < 8; n++) {
                h[n] = dA * h[n] + dx * Bv[n];
                y += h[n] * Cv[n];
                dA *= G;
            }
        } else {
#pragma unroll
            for (int n = 0; n < 8; n++) {
                float dA = __expf(dtv * a[n]);
                h[n] = dA * h[n] + dx * Bv[n];
                y += h[n] * Cv[n];
            }
        }
        y += __shfl_xor_sync(0xFFFFFFFFu, y, 1);
        float yy = y + xc * Dd;
        yy *= zv / (1.f + __expf(-zv));
        size_t oi = (row0 + l) * 1024 + d;
        __nv_bfloat16 hi = __float2bfloat16_rn(yy);
        if (half == 0) {
            g_ah[oi] = hi;
        } else {
            g_al[oi] = __float2bfloat16_rn(yy - __bfloat162float(hi));
        }
        xm3 = xm2; xm2 = xm1; xm1 = xs; xs = xn;
        dtv = dtn; zv = zn;
        Bv0 = nB0; Bv1 = nB1; Cv0 = nC0; Cv1 = nC1;
    }
}

// -- LayerNorm(512) over (inp [+ inp2] [+ res]); emits fp32 + bf16 hi/lo ---
__global__ void ln512_kernel(const float* __restrict__ inp,
                             const float* __restrict__ inp2,
                             const float* __restrict__ res,
                             const float* __restrict__ gam,
                             const float* __restrict__ bet,
                             float* __restrict__ out) {
    int row = blockIdx.x, tid = threadIdx.x;
    size_t base = (size_t)row * 512;
    float v0 = inp[base + tid], v1 = inp[base + tid + 256];
    if (inp2) { v0 += inp2[base + tid]; v1 += inp2[base + tid + 256]; }
    if (res)  { v0 += res[base + tid];  v1 += res[base + tid + 256]; }
    float s = v0 + v1, s2 = v0 * v0 + v1 * v1;
#pragma unroll
    for (int off = 16; off > 0; off >>= 1) {
        s  += __shfl_xor_sync(0xFFFFFFFFu, s, off);
        s2 += __shfl_xor_sync(0xFFFFFFFFu, s2, off);
    }
    __shared__ float ws[8][2];
    int wid = tid >> 5;
    if ((tid & 31) == 0) { ws[wid][0] = s; ws[wid][1] = s2; }
    __syncthreads();
    float S = 0.f, S2 = 0.f;
#pragma unroll
    for (int w = 0; w < 8; w++) { S += ws[w][0]; S2 += ws[w][1]; }
    float mu  = S * (1.f / 512.f);
    float var = S2 * (1.f / 512.f) - mu * mu;
    float inv = rsqrtf(var + 1e-5f);
    float o0 = (v0 - mu) * inv * gam[tid]       + bet[tid];
    float o1 = (v1 - mu) * inv * gam[tid + 256] + bet[tid + 256];
    out[base + tid]       = o0;
    out[base + tid + 256] = o1;
    __nv_bfloat16 h0, l0, h1, l1;
    split_hl(o0, h0, l0); split_hl(o1, h1, l1);
    g_ah[base + tid] = h0;       g_al[base + tid] = l0;
    g_ah[base + tid + 256] = h1; g_al[base + tid + 256] = l1;
}

// ---------------- mean pool over L ----------------------------------------
__global__ void pool_kernel() {
    int idx = blockIdx.x * 256 + threadIdx.x;
    int b = idx >> 9, d = idx & 511;
    float s = 0.f;
    for (int l = 0; l < L_TOK; l++)
        s += g_t[((size_t)b * L_TOK + l) * 512 + d];
    g_pool[idx] = s * (1.f / (float)L_TOK);
}

// ---------------- head ----------------------------------------------------
__global__ void head_kernel(const float* __restrict__ Wh,
                            const float* __restrict__ bh,
                            float* __restrict__ out) {
    int idx = threadIdx.x;
    if (idx >= BATCH * 10) return;
    int b = idx / 10, c = idx % 10;
    float s = bh[c];
    for (int k = 0; k < 512; k++)
        s += g_pool[b * 512 + k] * Wh[c * 512 + k];
    out[idx] = s;
}

// ---------------- launch ---------------------------------------------------
extern "C" void kernel_launch(void* const* d_in, const int* in_sizes, int n_in,
                              void* d_out, int out_size) {
    const float* x      = (const float*)d_in[0];
    const float* ln0_g  = (const float*)d_in[1];
    const float* ln0_b  = (const float*)d_in[2];
    const float* W_emb  = (const float*)d_in[3];
    const float* b_emb  = (const float*)d_in[4];
    const float* ln1_g  = (const float*)d_in[5];
    const float* ln1_b  = (const float*)d_in[6];
    const float* in_w   = (const float*)d_in[7];
    const float* conv_w = (const float*)d_in[8];
    const float* conv_b = (const float*)d_in[9];
    const float* xp_w   = (const float*)d_in[10];
    const float* dt_w   = (const float*)d_in[11];
    const float* dt_b   = (const float*)d_in[12];
    const float* A_log  = (const float*)d_in[13];
    const float* D_p    = (const float*)d_in[14];
    const float* out_w  = (const float*)d_in[15];
    const float* bln_g  = (const float*)d_in[16];
    const float* bln_b  = (const float*)d_in[17];
    const float* W_head = (const float*)d_in[18];
    const float* b_head = (const float*)d_in[19];
    float* out = (float*)d_out;

    float *t, *xz, *dtbc, *xpp, *dt, *mo;
    __nv_bfloat16 *ah, *al, *wh, *wl, *dh, *dl, *dwh, *dwl;
    cudaGetSymbolAddress((void**)&t,     g_t);
    cudaGetSymbolAddress((void**)&xz,    g_xz);
    cudaGetSymbolAddress((void**)&dtbc,  g_dtbc);
    cudaGetSymbolAddress((void**)&xpp,   g_xpp);
    cudaGetSymbolAddress((void**)&dt,    g_dt);
    cudaGetSymbolAddress((void**)&mo,    g_mo);
    cudaGetSymbolAddress((void**)&ah,    g_ah);
    cudaGetSymbolAddress((void**)&al,    g_al);
    cudaGetSymbolAddress((void**)&wh,    g_wh);
    cudaGetSymbolAddress((void**)&wl,    g_wl);
    cudaGetSymbolAddress((void**)&dh,    g_dh);
    cudaGetSymbolAddress((void**)&dl,    g_dl);
    cudaGetSymbolAddress((void**)&dwh,   g_dwh);
    cudaGetSymbolAddress((void**)&dwl,   g_dwl);

    cudaFuncSetAttribute(gemm_tc, cudaFuncAttributeMaxDynamicSharedMemorySize,
                         GEMM_SMEM);

    // ---- convert all weights to bf16 hi/lo upfront ----
    cvt_hl<<<(512 * PATCH_D) / 1024, 256>>>(
        (const float4*)W_emb, (uint2*)(wh + W_EMB_OFF), (uint2*)(wl + W_EMB_OFF));
    cvt_hl<<<(6 * 2048 * 512) / 1024, 256>>>(
        (const float4*)in_w, (uint2*)(wh + W_IN_OFF), (uint2*)(wl + W_IN_OFF));
    cvt_hl<<<(6 * 64 * 1024) / 1024, 256>>>(
        (const float4*)xp_w, (uint2*)(wh + W_XP_OFF), (uint2*)(wl + W_XP_OFF));
    cvt_hl<<<(6 * 512 * 1024) / 1024, 256>>>(
        (const float4*)out_w, (uint2*)(wh + W_OUT_OFF), (uint2*)(wl + W_OUT_OFF));
    cvt_pad_dtw<<<(N_LAYER * 1024 * 64) / 256, 256>>>(dt_w);

    // ---- patch embed (split-K x2, reduced inside ln512) ----
    patchify_ln_kernel<<<M_ROWS, 256>>>(x, ln0_g, ln0_b);
    gemm_tc<<<dim3(512 / 64, M_ROWS / 128, 2), 256, GEMM_SMEM>>>(
        ah, al, wh + W_EMB_OFF, wl + W_EMB_OFF, b_emb, mo, D_MODEL, PATCH_D,
        M_ROWS * D_MODEL, 0);
    ln512_kernel<<<M_ROWS, 256>>>(mo, mo + (size_t)M_ROWS * D_MODEL, nullptr,
                                  ln1_g, ln1_b, t);

    for (int i = 0; i < N_LAYER; i++) {
        const __nv_bfloat16* inWh = wh + W_IN_OFF  + (size_t)i * 2048 * 512;
        const __nv_bfloat16* inWl = wl + W_IN_OFF  + (size_t)i * 2048 * 512;
        const __nv_bfloat16* xpWh = wh + W_XP_OFF  + (size_t)i * 64 * 1024;
        const __nv_bfloat16* xpWl = wl + W_XP_OFF  + (size_t)i * 64 * 1024;
        const __nv_bfloat16* oWh  = wh + W_OUT_OFF + (size_t)i * 512 * 1024;
        const __nv_bfloat16* oWl  = wl + W_OUT_OFF + (size_t)i * 512 * 1024;
        const __nv_bfloat16* dWh  = dwh + (size_t)i * 1024 * 64;
        const __nv_bfloat16* dWl  = dwl + (size_t)i * 1024 * 64;
        const float* cW   = conv_w + (size_t)i * 1024 * 4;
        const float* cB   = conv_b + (size_t)i * 1024;
        const float* dtB  = dt_b + (size_t)i * 1024;
        const float* Ai   = A_log + (size_t)i * 1024 * 16;
        const float* Di   = D_p + (size_t)i * 1024;
        const float* bg   = bln_g + (size_t)i * 512;
        const float* bb   = bln_b + (size_t)i * 512;

        // xz = t @ in_proj^T : (6272,512) x (2048,512)
        gemm_tc<<<dim3(2048 / 64, M_ROWS / 128, 1), 256, GEMM_SMEM>>>(
            ah, al, inWh, inWl, nullptr, xz, 2048, 512, 0, 0);
        // conv + silu -> ah/al (bf16 hi/lo) for x_proj
        conv_silu_kernel<<<(M_ROWS * D_INNER) / 256, 256>>>(cW, cB);
        // x_dbl = xc @ x_proj^T : split-K x4, then reduce (+ bf16 hi/lo out)
        gemm_tc<<<dim3(1, M_ROWS / 128, 4), 256, GEMM_SMEM>>>(
            ah, al, xpWh, xpWl, nullptr, xpp, 64, 1024, M_ROWS * 64, 0);
        reduce_xp_kernel<<<(M_ROWS * 64 / 4) / 256, 256>>>();
        // dt = softplus(x_dbl_pad64 @ dt_w_pad64^T + dt_b) on tensor path
        gemm_tc<<<dim3(1024 / 64, M_ROWS / 128, 1), 256, GEMM_SMEM>>>(
            dh, dl, dWh, dWl, dtB, dt, 1024, 64, 0, 1);
        // scan (conv fused) -> y hi/lo in ah/al
        scan_kernel<<<1024, 64>>>(Ai, Di, cW, cB);
        // out = y @ out_proj^T : split-K x2, reduced inside ln512
        gemm_tc<<<dim3(512 / 64, M_ROWS / 128, 2), 256, GEMM_SMEM>>>(
            ah, al, oWh, oWl, nullptr, mo, D_MODEL, 1024, M_ROWS * D_MODEL, 0);
        ln512_kernel<<<M_ROWS, 256>>>(mo, mo + (size_t)M_ROWS * D_MODEL, t,
                                      bg, bb, t);
    }

    pool_kernel<<<(BATCH * D_MODEL) / 256, 256>>>();
    head_kernel<<<1, 320>>>(W_head, b_head, out);
}

// round 17
// speedup vs baseline: 1.3691x; 1.3431x over previous
#include <cuda_runtime.h>
#include <cuda_fp16.h>
#include <math.h>
#include <stdint.h>

#define BATCH   32
#define L_TOK   196
#define D_MODEL 512
#define D_INNER 1024
#define PATCH_D 768
#define N_STATE 16
#define N_LAYER 6
#define M_ROWS  (BATCH * L_TOK)   // 6272

// ---------------- scratch (static device globals; no allocation) ----------
static __device__ float g_t    [M_ROWS * D_MODEL];
static __device__ float g_xz   [M_ROWS * 2 * D_INNER];
static __device__ float g_dtbc [M_ROWS * 64];
static __device__ float g_xpp  [4 * M_ROWS * 64];     // split-K partials
static __device__ float g_dt   [M_ROWS * D_INNER];
static __device__ float g_mo   [2 * M_ROWS * D_MODEL];  // split-K x2 partials
static __device__ float g_pool [BATCH * D_MODEL];
static __device__ __align__(16) __half g_aq[M_ROWS * D_INNER];   // fp16 activations
// all weights fp16, converted once per call:
#define W_EMB_OFF 0
#define W_IN_OFF  (512 * 768)
#define W_XP_OFF  (W_IN_OFF + 6 * 2048 * 512)
#define W_OUT_OFF (W_XP_OFF + 6 * 64 * 1024)
#define W_TOTAL   (W_OUT_OFF + 6 * 512 * 1024)
static __device__ __align__(16) __half g_wq[W_TOTAL];

// ---------------- fp32 -> fp16 convert (x4) --------------------------------
__global__ void cvt_h(const float4* __restrict__ s, uint2* __restrict__ q) {
    int i = blockIdx.x * 256 + threadIdx.x;
    float4 v = s[i];
    __half2 lo = __floats2half2_rn(v.x, v.y);
    __half2 hi = __floats2half2_rn(v.z, v.w);
    uint2 o;
    o.x = *(uint32_t*)&lo;
    o.y = *(uint32_t*)&hi;
    q[i] = o;
}

// ---------------- HMMA helpers --------------------------------------------
__device__ __forceinline__ uint32_t smem_u32(const void* p) {
    uint32_t a;
    asm("{ .reg .u64 t; cvta.to.shared.u64 t, %1; cvt.u32.u64 %0, t; }"
        : "=r"(a) : "l"(p));
    return a;
}
__device__ __forceinline__ void ldm_x4(uint32_t* r, uint32_t addr) {
    asm volatile("ldmatrix.sync.aligned.m8n8.x4.shared.b16 {%0,%1,%2,%3}, [%4];"
                 : "=r"(r[0]), "=r"(r[1]), "=r"(r[2]), "=r"(r[3]) : "r"(addr));
}
__device__ __forceinline__ void mma_f16(float* d, const uint32_t* a,
                                        uint32_t b0, uint32_t b1) {
    asm volatile("mma.sync.aligned.m16n8k16.row.col.f32.f16.f16.f32 "
                 "{%0,%1,%2,%3}, {%4,%5,%6,%7}, {%8,%9}, {%0,%1,%2,%3};"
                 : "+f"(d[0]), "+f"(d[1]), "+f"(d[2]), "+f"(d[3])
                 : "r"(a[0]), "r"(a[1]), "r"(a[2]), "r"(a[3]), "r"(b0), "r"(b1));
}

// ===== fp16 HMMA GEMM: C[M,N] = A[M,K] @ W[N,K]^T =========================
// 256 threads, tile 128x64, BK=64, 2-stage cp.async, 2 CTAs/SM.
// 8 warps, warp tile 16x64. Row stride 144B -> ldmatrix conflict-free.
// Optional split-K over gridDim.z (bias applied on z==0 only).
#define ROWB 144
#define OFF_B 18432
#define STG_BYTES 27648
#define GEMM_SMEM (2 * STG_BYTES)   // 55296

__global__ void __launch_bounds__(256, 2) gemm_tc(
    const __half* __restrict__ A, const __half* __restrict__ B,
    const float* __restrict__ bias,
    float* __restrict__ C, int ldc, int K, int czstride)
{
    extern __shared__ char smem[];
    const uint32_t sbase = smem_u32(smem);
    const int tid = threadIdx.x;
    const int wid = tid >> 5, lane = tid & 31;
    const int m0 = blockIdx.y * 128, n0 = blockIdx.x * 64;
    const int kseg = K / gridDim.z;
    const int kb = blockIdx.z * kseg;
    C += (size_t)blockIdx.z * czstride;

    float acc[8][4];
#pragma unroll
    for (int j = 0; j < 8; j++)
#pragma unroll
        for (int q = 0; q < 4; q++) acc[j][q] = 0.f;

    const int niter = kseg >> 6;
    const int lr  = tid >> 3;          // 0..31
    const int kc16 = (tid & 7) * 16;
    const int kcel = (tid & 7) * 8;

    auto load_stage = [&](int st, int it) {
        uint32_t sb = sbase + st * STG_BYTES;
        const int k0 = kb + (it << 6);
#pragma unroll
        for (int q = 0; q < 4; q++) {          // A rows: 4 batches of 32
            int r = lr + q * 32;
            size_t gA = (size_t)(m0 + r) * K + k0 + kcel;
            uint32_t so = (uint32_t)(r * ROWB + kc16);
            asm volatile("cp.async.cg.shared.global [%0], [%1], 16;"
                         :: "r"(sb + so), "l"(A + gA) : "memory");
        }
#pragma unroll
        for (int q = 0; q < 2; q++) {          // B rows: 2 batches of 32
            int r = lr + q * 32;
            size_t gB = (size_t)(n0 + r) * K + k0 + kcel;
            uint32_t so = (uint32_t)(r * ROWB + kc16);
            asm volatile("cp.async.cg.shared.global [%0], [%1], 16;"
                         :: "r"(sb + OFF_B + so), "l"(B + gB) : "memory");
        }
        asm volatile("cp.async.commit_group;" ::: "memory");
    };

    load_stage(0, 0);

    const uint32_t aoff = (uint32_t)((wid * 16 + (lane & 15)) * ROWB + (lane >> 4) * 16);
    const uint32_t boff = (uint32_t)(((lane & 7) + ((lane & 16) >> 1)) * ROWB
                                     + ((lane & 8) ? 16 : 0));

    for (int it = 0; it < niter; it++) {
        if (it + 1 < niter) {
            load_stage((it + 1) & 1, it + 1);
            asm volatile("cp.async.wait_group 1;" ::: "memory");
        } else {
            asm volatile("cp.async.wait_group 0;" ::: "memory");
        }
        __syncthreads();

        uint32_t sb = sbase + (it & 1) * STG_BYTES;
        uint32_t sA = sb + aoff;
        uint32_t sB = sb + OFF_B + boff;
#pragma unroll
        for (int ks = 0; ks < 4; ks++) {
            uint32_t kbq = ks * 32;            // 16 fp16 = 32B per k-step
            uint32_t a[4];
            ldm_x4(a, sA + kbq);
#pragma unroll
            for (int nt = 0; nt < 4; nt++) {
                uint32_t bf[4];
                ldm_x4(bf, sB + nt * (16 * ROWB) + kbq);
                mma_f16(acc[2 * nt + 0], a, bf[0], bf[1]);
                mma_f16(acc[2 * nt + 1], a, bf[2], bf[3]);
            }
        }
        __syncthreads();
    }

    const bool addb = (bias != nullptr) && (blockIdx.z == 0);
    const int mrow = m0 + wid * 16 + (lane >> 2);
    const int ncol = n0 + (lane & 3) * 2;
#pragma unroll
    for (int j = 0; j < 8; j++) {
        int c = ncol + j * 8;
        float b0 = 0.f, b1 = 0.f;
        if (addb) { b0 = __ldg(&bias[c]); b1 = __ldg(&bias[c + 1]); }
        float2 v0 = make_float2(acc[j][0] + b0, acc[j][1] + b1);
        float2 v1 = make_float2(acc[j][2] + b0, acc[j][3] + b1);
        *(float2*)&C[(size_t)mrow * ldc + c] = v0;
        *(float2*)&C[(size_t)(mrow + 8) * ldc + c] = v1;
    }
}

// ------------- reduce split-K partials: dtbc = sum of 4 chunks ------------
__global__ void reduce_xp_kernel() {
    int i = blockIdx.x * 256 + threadIdx.x;
    const float4* p = (const float4*)g_xpp;
    const int S = M_ROWS * 64 / 4;
    float4 a = p[i], b = p[i + S], c = p[i + 2 * S], d = p[i + 3 * S];
    float4 r;
    r.x = (a.x + b.x) + (c.x + d.x);
    r.y = (a.y + b.y) + (c.y + d.y);
    r.z = (a.z + b.z) + (c.z + d.z);
    r.w = (a.w + b.w) + (c.w + d.w);
    ((float4*)g_dtbc)[i] = r;
}

// ---------------- patchify + LayerNorm(768) -> fp16 -----------------------
__global__ void patchify_ln_kernel(const float* __restrict__ x,
                                   const float* __restrict__ gam,
                                   const float* __restrict__ bet) {
    int row = blockIdx.x;
    int b = row / L_TOK, l = row % L_TOK;
    int gh = l / 14, gw = l % 14;
    int tid = threadIdx.x;
    float v[3];
    float s = 0.f, s2 = 0.f;
#pragma unroll
    for (int i = 0; i < 3; i++) {
        int e = tid + i * 256;
        int c = e >> 8, rem = e & 255;
        int p1 = rem >> 4, p2 = rem & 15;
        float val = x[(((size_t)b * 3 + c) * 224 + gh * 16 + p1) * 224 + gw * 16 + p2];
        v[i] = val; s += val; s2 += val * val;
    }
#pragma unroll
    for (int off = 16; off > 0; off >>= 1) {
        s  += __shfl_xor_sync(0xFFFFFFFFu, s, off);
        s2 += __shfl_xor_sync(0xFFFFFFFFu, s2, off);
    }
    __shared__ float ws[8][2];
    int wid = tid >> 5;
    if ((tid & 31) == 0) { ws[wid][0] = s; ws[wid][1] = s2; }
    __syncthreads();
    float S = 0.f, S2 = 0.f;
#pragma unroll
    for (int w = 0; w < 8; w++) { S += ws[w][0]; S2 += ws[w][1]; }
    float mu  = S * (1.f / 768.f);
    float var = S2 * (1.f / 768.f) - mu * mu;
    float inv = rsqrtf(var + 1e-5f);
#pragma unroll
    for (int i = 0; i < 3; i++) {
        int e = tid + i * 256;
        float o = (v[i] - mu) * inv * gam[e] + bet[e];
        g_aq[(size_t)row * PATCH_D + e] = __float2half_rn(o);
    }
}

// ---------------- small fp32 NT GEMM (dt_proj) ----------------------------
template<int BM, int BN, int BK, int TM, int TN, int EPI>
__global__ void __launch_bounds__(256) gemm_nt(
    const float* __restrict__ A, int lda,
    const float* __restrict__ W, int Kd,
    const float* __restrict__ bias,
    float* __restrict__ C, int ldc)
{
    __shared__ float As[BK][BM + 4];
    __shared__ float Bs[BK][BN + 4];
    const int m0 = blockIdx.y * BM, n0 = blockIdx.x * BN;
    const int tid = threadIdx.x;
    const int tx = tid & 15, ty = tid >> 4;
    constexpr int KQ = BK / 4;
    const int lrow = tid / KQ;
    const int kq   = (tid % KQ) * 4;

    float acc[TM][TN];
#pragma unroll
    for (int i = 0; i < TM; i++)
#pragma unroll
        for (int j = 0; j < TN; j++) acc[i][j] = 0.f;

    const float* Aptr = A + (size_t)(m0 + lrow) * lda + kq;
    const float* Wptr = W + (size_t)(n0 + lrow) * Kd  + kq;

    for (int k0 = 0; k0 < Kd; k0 += BK) {
        float4 a4 = *(const float4*)(Aptr + k0);
        float4 b4 = *(const float4*)(Wptr + k0);
        As[kq + 0][lrow] = a4.x; As[kq + 1][lrow] = a4.y;
        As[kq + 2][lrow] = a4.z; As[kq + 3][lrow] = a4.w;
        Bs[kq + 0][lrow] = b4.x; Bs[kq + 1][lrow] = b4.y;
        Bs[kq + 2][lrow] = b4.z; Bs[kq + 3][lrow] = b4.w;
        __syncthreads();
#pragma unroll
        for (int k = 0; k < BK; k++) {
            float ra[TM], rb[TN];
#pragma unroll
            for (int i = 0; i < TM; i++) ra[i] = As[k][ty + 16 * i];
#pragma unroll
            for (int j = 0; j < TN; j++) rb[j] = Bs[k][tx + 16 * j];
#pragma unroll
            for (int i = 0; i < TM; i++)
#pragma unroll
                for (int j = 0; j < TN; j++) acc[i][j] += ra[i] * rb[j];
        }
        __syncthreads();
    }
#pragma unroll
    for (int i = 0; i < TM; i++) {
        int r = m0 + ty + 16 * i;
#pragma unroll
        for (int j = 0; j < TN; j++) {
            int cc = n0 + tx + 16 * j;
            float v = acc[i][j];
            if (bias) v += __ldg(&bias[cc]);
            if (EPI == 1) v = (v > 20.f) ? v : log1pf(__expf(v));
            C[(size_t)r * ldc + cc] = v;
        }
    }
}

// -------- causal depthwise conv (K=4) + SiLU -> fp16 ----------------------
__global__ void conv_silu_kernel(const float* __restrict__ cw,
                                 const float* __restrict__ cb) {
    int idx = blockIdx.x * 256 + threadIdx.x;
    int d  = idx & (D_INNER - 1);
    int bl = idx >> 10;
    int l  = bl % L_TOK;
    float w0 = cw[d * 4 + 0], w1 = cw[d * 4 + 1];
    float w2 = cw[d * 4 + 2], w3 = cw[d * 4 + 3];
    size_t base = (size_t)bl * 2048 + d;
    float s = cb[d];
    if (l >= 3) s += w0 * g_xz[base - 3 * 2048];
    if (l >= 2) s += w1 * g_xz[base - 2 * 2048];
    if (l >= 1) s += w2 * g_xz[base - 1 * 2048];
    s += w3 * g_xz[base];
    s = s / (1.f + __expf(-s));
    g_aq[idx] = __float2half_rn(s);
}

// --- selective scan, fused causal conv+silu; 2 threads per (b,d) ----------
__global__ void __launch_bounds__(64) scan_kernel(
    const float* __restrict__ A_log, const float* __restrict__ Dv,
    const float* __restrict__ cw, const float* __restrict__ cb)
{
    int t = blockIdx.x * 64 + threadIdx.x;       // 65536 threads
    int half = t & 1;
    int bd = t >> 1;
    int b = bd >> 10, d = bd & 1023;
    int n0 = half * 8;
    float a[8], h[8];
#pragma unroll
    for (int n = 0; n < 8; n++) {
        a[n] = -__expf(__ldg(&A_log[d * N_STATE + n0 + n]));
        h[n] = 0.f;
    }
    float a0 = a[0];
    float delta = (a[7] - a[0]) * (1.f / 7.f);
    bool ap = true;
#pragma unroll
    for (int n = 0; n < 8; n++)
        ap = ap && (fabsf(a[n] - (a0 + n * delta)) <= 1e-5f * fmaxf(fabsf(a[n]), 1e-3f));

    float w0 = __ldg(&cw[d * 4 + 0]), w1 = __ldg(&cw[d * 4 + 1]);
    float w2 = __ldg(&cw[d * 4 + 2]), w3 = __ldg(&cw[d * 4 + 3]);
    float cbd = __ldg(&cb[d]);
    float Dd = __ldg(&Dv[d]);
    size_t row0 = (size_t)b * L_TOK;

    float dtv = g_dt[row0 * 1024 + d];
    float xs  = g_xz[row0 * 2048 + d];
    float zv  = g_xz[row0 * 2048 + 1024 + d];
    float xm1 = 0.f, xm2 = 0.f, xm3 = 0.f;
    const float4* bc4 = (const float4*)(g_dtbc + row0 * 64 + 32 + n0);
    float4 Bv0 = bc4[0], Bv1 = bc4[1];
    float4 Cv0 = bc4[4], Cv1 = bc4[5];
    for (int l = 0; l < L_TOK; l++) {
        float dtn = 0.f, xn = 0.f, zn = 0.f;
        float4 nB0, nB1, nC0, nC1;
        if (l + 1 < L_TOK) {
            size_t rn = row0 + l + 1;
            dtn = g_dt[rn * 1024 + d];
            xn  = g_xz[rn * 2048 + d];
            zn  = g_xz[rn * 2048 + 1024 + d];
            const float4* nbc = (const float4*)(g_dtbc + rn * 64 + 32 + n0);
            nB0 = nbc[0]; nB1 = nbc[1]; nC0 = nbc[4]; nC1 = nbc[5];
        }
        float xc = cbd + w0 * xm3 + w1 * xm2 + w2 * xm1 + w3 * xs;
        xc = xc / (1.f + __expf(-xc));

        float Bv[8] = {Bv0.x, Bv0.y, Bv0.z, Bv0.w, Bv1.x, Bv1.y, Bv1.z, Bv1.w};
        float Cv[8] = {Cv0.x, Cv0.y, Cv0.z, Cv0.w, Cv1.x, Cv1.y, Cv1.z, Cv1.w};
        float dx = dtv * xc;
        float y = 0.f;
        if (ap) {
            float dA = __expf(dtv * a0);
            float G  = __expf(dtv * delta);
#pragma unroll
            for (int n = 0; n < 8; n++) {
                h[n] = dA * h[n] + dx * Bv[n];
                y += h[n] * Cv[n];
                dA *= G;
            }
        } else {
#pragma unroll
            for (int n = 0; n < 8; n++) {
                float dA = __expf(dtv * a[n]);
                h[n] = dA * h[n] + dx * Bv[n];
                y += h[n] * Cv[n];
            }
        }
        y += __shfl_xor_sync(0xFFFFFFFFu, y, 1);
        if (half == 0) {
            float yy = y + xc * Dd;
            yy *= zv / (1.f + __expf(-zv));
            g_aq[(row0 + l) * 1024 + d] = __float2half_rn(yy);
        }
        xm3 = xm2; xm2 = xm1; xm1 = xs; xs = xn;
        dtv = dtn; zv = zn;
        Bv0 = nB0; Bv1 = nB1; Cv0 = nC0; Cv1 = nC1;
    }
}

// -- LayerNorm(512) over (inp [+ inp2] [+ res]); emits fp32 + fp16 ---------
__global__ void ln512_kernel(const float* __restrict__ inp,
                             const float* __restrict__ inp2,
                             const float* __restrict__ res,
                             const float* __restrict__ gam,
                             const float* __restrict__ bet,
                             float* __restrict__ out) {
    int row = blockIdx.x, tid = threadIdx.x;
    size_t base = (size_t)row * 512;
    float v0 = inp[base + tid], v1 = inp[base + tid + 256];
    if (inp2) { v0 += inp2[base + tid]; v1 += inp2[base + tid + 256]; }
    if (res)  { v0 += res[base + tid];  v1 += res[base + tid + 256]; }
    float s = v0 + v1, s2 = v0 * v0 + v1 * v1;
#pragma unroll
    for (int off = 16; off > 0; off >>= 1) {
        s  += __shfl_xor_sync(0xFFFFFFFFu, s, off);
        s2 += __shfl_xor_sync(0xFFFFFFFFu, s2, off);
    }
    __shared__ float ws[8][2];
    int wid = tid >> 5;
    if ((tid & 31) == 0) { ws[wid][0] = s; ws[wid][1] = s2; }
    __syncthreads();
    float S = 0.f, S2 = 0.f;
#pragma unroll
    for (int w = 0; w < 8; w++) { S += ws[w][0]; S2 += ws[w][1]; }
    float mu  = S * (1.f / 512.f);
    float var = S2 * (1.f / 512.f) - mu * mu;
    float inv = rsqrtf(var + 1e-5f);
    float o0 = (v0 - mu) * inv * gam[tid]       + bet[tid];
    float o1 = (v1 - mu) * inv * gam[tid + 256] + bet[tid + 256];
    out[base + tid]       = o0;
    out[base + tid + 256] = o1;
    g_aq[base + tid]       = __float2half_rn(o0);
    g_aq[base + tid + 256] = __float2half_rn(o1);
}

// ---------------- mean pool over L ----------------------------------------
__global__ void pool_kernel() {
    int idx = blockIdx.x * 256 + threadIdx.x;
    int b = idx >> 9, d = idx & 511;
    float s = 0.f;
    for (int l = 0; l < L_TOK; l++)
        s += g_t[((size_t)b * L_TOK + l) * 512 + d];
    g_pool[idx] = s * (1.f / (float)L_TOK);
}

// ---------------- head ----------------------------------------------------
__global__ void head_kernel(const float* __restrict__ Wh,
                            const float* __restrict__ bh,
                            float* __restrict__ out) {
    int idx = threadIdx.x;
    if (idx >= BATCH * 10) return;
    int b = idx / 10, c = idx % 10;
    float s = bh[c];
    for (int k = 0; k < 512; k++)
        s += g_pool[b * 512 + k] * Wh[c * 512 + k];
    out[idx] = s;
}

// ---------------- launch ---------------------------------------------------
extern "C" void kernel_launch(void* const* d_in, const int* in_sizes, int n_in,
                              void* d_out, int out_size) {
    const float* x      = (const float*)d_in[0];
    const float* ln0_g  = (const float*)d_in[1];
    const float* ln0_b  = (const float*)d_in[2];
    const float* W_emb  = (const float*)d_in[3];
    const float* b_emb  = (const float*)d_in[4];
    const float* ln1_g  = (const float*)d_in[5];
    const float* ln1_b  = (const float*)d_in[6];
    const float* in_w   = (const float*)d_in[7];
    const float* conv_w = (const float*)d_in[8];
    const float* conv_b = (const float*)d_in[9];
    const float* xp_w   = (const float*)d_in[10];
    const float* dt_w   = (const float*)d_in[11];
    const float* dt_b   = (const float*)d_in[12];
    const float* A_log  = (const float*)d_in[13];
    const float* D_p    = (const float*)d_in[14];
    const float* out_w  = (const float*)d_in[15];
    const float* bln_g  = (const float*)d_in[16];
    const float* bln_b  = (const float*)d_in[17];
    const float* W_head = (const float*)d_in[18];
    const float* b_head = (const float*)d_in[19];
    float* out = (float*)d_out;

    float *t, *xz, *dtbc, *xpp, *dt, *mo;
    __half *aq, *wq;
    cudaGetSymbolAddress((void**)&t,     g_t);
    cudaGetSymbolAddress((void**)&xz,    g_xz);
    cudaGetSymbolAddress((void**)&dtbc,  g_dtbc);
    cudaGetSymbolAddress((void**)&xpp,   g_xpp);
    cudaGetSymbolAddress((void**)&dt,    g_dt);
    cudaGetSymbolAddress((void**)&mo,    g_mo);
    cudaGetSymbolAddress((void**)&aq,    g_aq);
    cudaGetSymbolAddress((void**)&wq,    g_wq);

    cudaFuncSetAttribute(gemm_tc, cudaFuncAttributeMaxDynamicSharedMemorySize,
                         GEMM_SMEM);

    // ---- convert all weights to fp16 upfront ----
    cvt_h<<<(512 * PATCH_D) / 1024, 256>>>(
        (const float4*)W_emb, (uint2*)(wq + W_EMB_OFF));
    cvt_h<<<(6 * 2048 * 512) / 1024, 256>>>(
        (const float4*)in_w, (uint2*)(wq + W_IN_OFF));
    cvt_h<<<(6 * 64 * 1024) / 1024, 256>>>(
        (const float4*)xp_w, (uint2*)(wq + W_XP_OFF));
    cvt_h<<<(6 * 512 * 1024) / 1024, 256>>>(
        (const float4*)out_w, (uint2*)(wq + W_OUT_OFF));

    // ---- patch embed (split-K x2, reduced inside ln512) ----
    patchify_ln_kernel<<<M_ROWS, 256>>>(x, ln0_g, ln0_b);
    gemm_tc<<<dim3(512 / 64, M_ROWS / 128, 2), 256, GEMM_SMEM>>>(
        aq, wq + W_EMB_OFF, b_emb, mo, D_MODEL, PATCH_D, M_ROWS * D_MODEL);
    ln512_kernel<<<M_ROWS, 256>>>(mo, mo + (size_t)M_ROWS * D_MODEL, nullptr,
                                  ln1_g, ln1_b, t);

    for (int i = 0; i < N_LAYER; i++) {
        const __half* inW = wq + W_IN_OFF  + (size_t)i * 2048 * 512;
        const __half* xpW = wq + W_XP_OFF  + (size_t)i * 64 * 1024;
        const __half* oW  = wq + W_OUT_OFF + (size_t)i * 512 * 1024;
        const float* cW   = conv_w + (size_t)i * 1024 * 4;
        const float* cB   = conv_b + (size_t)i * 1024;
        const float* dtW  = dt_w + (size_t)i * 1024 * 32;
        const float* dtB  = dt_b + (size_t)i * 1024;
        const float* Ai   = A_log + (size_t)i * 1024 * 16;
        const float* Di   = D_p + (size_t)i * 1024;
        const float* bg   = bln_g + (size_t)i * 512;
        const float* bb   = bln_b + (size_t)i * 512;

        // xz = t @ in_proj^T : (6272,512) x (2048,512)
        gemm_tc<<<dim3(2048 / 64, M_ROWS / 128, 1), 256, GEMM_SMEM>>>(
            aq, inW, nullptr, xz, 2048, 512, 0);
        // conv + silu -> aq (fp16) for x_proj
        conv_silu_kernel<<<(M_ROWS * D_INNER) / 256, 256>>>(cW, cB);
        // x_dbl = xc @ x_proj^T : split-K x4, then reduce
        gemm_tc<<<dim3(1, M_ROWS / 128, 4), 256, GEMM_SMEM>>>(
            aq, xpW, nullptr, xpp, 64, 1024, M_ROWS * 64);
        reduce_xp_kernel<<<(M_ROWS * 64 / 4) / 256, 256>>>();
        // dt = softplus(x_dbl[:, :32] @ dt_proj^T + dt_b)
        gemm_nt<64,64,16,4,4,1><<<dim3(1024 / 64, M_ROWS / 64), 256>>>(
            dtbc, 64, dtW, 32, dtB, dt, D_INNER);
        // scan (conv fused) -> y fp16 in aq
        scan_kernel<<<1024, 64>>>(Ai, Di, cW, cB);
        // out = y @ out_proj^T : split-K x2, reduced inside ln512
        gemm_tc<<<dim3(512 / 64, M_ROWS / 128, 2), 256, GEMM_SMEM>>>(
            aq, oW, nullptr, mo, D_MODEL, 1024, M_ROWS * D_MODEL);
        ln512_kernel<<<M_ROWS, 256>>>(mo, mo + (size_t)M_ROWS * D_MODEL, t,
                                      bg, bb, t);
    }

    pool_kernel<<<(BATCH * D_MODEL) / 256, 256>>>();
    head_kernel<<<1, 320>>>(W_head, b_head, out);
}